// round 1
// baseline (speedup 1.0000x reference)
#include <cuda_runtime.h>
#include <math.h>

#define BATCH 32768
#define HID   2048

// 268 MB scratch for h1 = tanh(concat @ W1 + b1)
__device__ float g_h1[(size_t)BATCH * HID];

// ---------------------------------------------------------------------------
// out[b] = bc[0]  (logits bias; GEMM epilogue atomically accumulates on top)
// ---------------------------------------------------------------------------
__global__ void init_logits_kernel(const float* __restrict__ bc, float* __restrict__ out) {
    int i = blockIdx.x * 256 + threadIdx.x;
    out[i] = bc[0];
}

// ---------------------------------------------------------------------------
// Layer 1: h1[b,k] = tanh(x0*W1[0,k] + x1*W1[1,k] + cos(x0)*W1[2,k]
//                       + cos(x0)cos(x1)*W1[3,k] + W1[4,k] + W1[5,k] + b1[k])
// (quantum feature map in closed form; padded wires give cos(0)=1)
// ---------------------------------------------------------------------------
__global__ void layer1_kernel(const float* __restrict__ x,
                              const float* __restrict__ W1,
                              const float* __restrict__ b1) {
    int b = blockIdx.y;
    int k = (blockIdx.x * 256 + threadIdx.x) * 4;
    float x0 = x[2 * b];
    float x1 = x[2 * b + 1];
    float c0  = cosf(x0);
    float c01 = c0 * cosf(x1);

    float4 w0 = *(const float4*)(W1 + 0 * HID + k);
    float4 w1 = *(const float4*)(W1 + 1 * HID + k);
    float4 w2 = *(const float4*)(W1 + 2 * HID + k);
    float4 w3 = *(const float4*)(W1 + 3 * HID + k);
    float4 w4 = *(const float4*)(W1 + 4 * HID + k);
    float4 w5 = *(const float4*)(W1 + 5 * HID + k);
    float4 bb = *(const float4*)(b1 + k);

    float4 r;
    r.x = tanhf(x0 * w0.x + x1 * w1.x + c0 * w2.x + c01 * w3.x + w4.x + w5.x + bb.x);
    r.y = tanhf(x0 * w0.y + x1 * w1.y + c0 * w2.y + c01 * w3.y + w4.y + w5.y + bb.y);
    r.z = tanhf(x0 * w0.z + x1 * w1.z + c0 * w2.z + c01 * w3.z + w4.z + w5.z + bb.z);
    r.w = tanhf(x0 * w0.w + x1 * w1.w + c0 * w2.w + c01 * w3.w + w4.w + w5.w + bb.w);
    *(float4*)(g_h1 + (size_t)b * HID + k) = r;
}

// ---------------------------------------------------------------------------
// GEMM2 + fused epilogue:
//   h2 = tanh(h1 @ W2 + b2)   (never materialized)
//   out[row] += sum_col h2[row,col] * Wc[col]
// 128x128 block tile, BK=16, 256 threads, 8x8 per thread.
// ---------------------------------------------------------------------------
#define BM 128
#define BN 128
#define BK 16

__global__ __launch_bounds__(256, 2)
void gemm2_fused_kernel(const float* __restrict__ W2,
                        const float* __restrict__ b2,
                        const float* __restrict__ Wc,
                        float* __restrict__ out) {
    __shared__ float As[BK][BM];
    __shared__ float Bs[BK][BN];

    const int bx = blockIdx.x;          // N tile (16)
    const int by = blockIdx.y;          // M tile (256)
    const int tid = threadIdx.x;
    const int tx = tid & 15;            // 0..15
    const int ty = tid >> 4;            // 0..15
    const int row0 = by * BM;
    const int col0 = bx * BN;

    const float* A = g_h1;

    float acc[8][8];
    #pragma unroll
    for (int i = 0; i < 8; i++)
        #pragma unroll
        for (int j = 0; j < 8; j++)
            acc[i][j] = 0.f;

    for (int k0 = 0; k0 < HID; k0 += BK) {
        // A tile: 128 rows x 16 k  (512 float4s / 256 threads = 2 each)
        #pragma unroll
        for (int l = 0; l < 2; l++) {
            int f  = tid + l * 256;       // float4 id
            int r  = f >> 2;              // row 0..127
            int kq = (f & 3) << 2;        // k offset 0,4,8,12
            float4 v = *(const float4*)(A + (size_t)(row0 + r) * HID + k0 + kq);
            As[kq + 0][r] = v.x;
            As[kq + 1][r] = v.y;
            As[kq + 2][r] = v.z;
            As[kq + 3][r] = v.w;
        }
        // B tile: 16 k x 128 n
        #pragma unroll
        for (int l = 0; l < 2; l++) {
            int f = tid + l * 256;
            int r = f >> 5;               // k row 0..15
            int c = (f & 31) << 2;        // col 0..124
            *(float4*)(&Bs[r][c]) = *(const float4*)(W2 + (size_t)(k0 + r) * HID + col0 + c);
        }
        __syncthreads();

        #pragma unroll
        for (int kk = 0; kk < BK; kk++) {
            float a[8], bfr[8];
            #pragma unroll
            for (int i = 0; i < 8; i++) a[i]   = As[kk][ty * 8 + i];
            #pragma unroll
            for (int j = 0; j < 8; j++) bfr[j] = Bs[kk][tx * 8 + j];
            #pragma unroll
            for (int i = 0; i < 8; i++)
                #pragma unroll
                for (int j = 0; j < 8; j++)
                    acc[i][j] += a[i] * bfr[j];
        }
        __syncthreads();
    }

    // Epilogue: tanh + bias, dot with Wc slice, reduce across the 16 tx lanes.
    float wc[8], bb[8];
    #pragma unroll
    for (int j = 0; j < 8; j++) {
        int c = col0 + tx * 8 + j;
        wc[j] = Wc[c];
        bb[j] = b2[c];
    }
    #pragma unroll
    for (int i = 0; i < 8; i++) {
        float part = 0.f;
        #pragma unroll
        for (int j = 0; j < 8; j++) {
            float h = tanhf(acc[i][j] + bb[j]);
            part += h * wc[j];
        }
        // reduce over 16-lane segments (tx dimension)
        #pragma unroll
        for (int off = 8; off > 0; off >>= 1)
            part += __shfl_down_sync(0xffffffffu, part, off, 16);
        if (tx == 0)
            atomicAdd(&out[row0 + ty * 8 + i], part);
    }
}

// ---------------------------------------------------------------------------
// Risk head: tiny 2->8->4->1 MLP, one thread per row. out[B + b] = risk.
// ---------------------------------------------------------------------------
__global__ void risk_kernel(const float* __restrict__ x,
                            const float* __restrict__ Wr1, const float* __restrict__ br1,
                            const float* __restrict__ Wr2, const float* __restrict__ br2,
                            const float* __restrict__ Wr3, const float* __restrict__ br3,
                            float* __restrict__ out) {
    int b = blockIdx.x * 256 + threadIdx.x;
    float x0 = x[2 * b], x1 = x[2 * b + 1];

    float r1[8];
    #pragma unroll
    for (int j = 0; j < 8; j++)
        r1[j] = tanhf(x0 * Wr1[j] + x1 * Wr1[8 + j] + br1[j]);

    float r2[4];
    #pragma unroll
    for (int m = 0; m < 4; m++) {
        float s = br2[m];
        #pragma unroll
        for (int j = 0; j < 8; j++)
            s += r1[j] * Wr2[j * 4 + m];
        r2[m] = tanhf(s);
    }

    float risk = br3[0];
    #pragma unroll
    for (int m = 0; m < 4; m++)
        risk += r2[m] * Wr3[m];

    out[BATCH + b] = risk;
}

// ---------------------------------------------------------------------------
extern "C" void kernel_launch(void* const* d_in, const int* in_sizes, int n_in,
                              void* d_out, int out_size) {
    const float* x   = (const float*)d_in[0];
    const float* W1  = (const float*)d_in[1];
    const float* b1  = (const float*)d_in[2];
    const float* W2  = (const float*)d_in[3];
    const float* b2  = (const float*)d_in[4];
    const float* Wc  = (const float*)d_in[5];
    const float* bc  = (const float*)d_in[6];
    const float* Wr1 = (const float*)d_in[7];
    const float* br1 = (const float*)d_in[8];
    const float* Wr2 = (const float*)d_in[9];
    const float* br2 = (const float*)d_in[10];
    const float* Wr3 = (const float*)d_in[11];
    const float* br3 = (const float*)d_in[12];
    float* out = (float*)d_out;

    init_logits_kernel<<<BATCH / 256, 256>>>(bc, out);
    layer1_kernel<<<dim3(HID / (256 * 4), BATCH), 256>>>(x, W1, b1);
    gemm2_fused_kernel<<<dim3(HID / BN, BATCH / BM), 256>>>(W2, b2, Wc, out);
    risk_kernel<<<BATCH / 256, 256>>>(x, Wr1, br1, Wr2, br2, Wr3, br3, out);
}

// round 4
// speedup vs baseline: 2.3393x; 2.3393x over previous
#include <cuda_runtime.h>
#include <cuda_bf16.h>
#include <math.h>
#include <stdint.h>

#define BATCH 32768
#define HID   2048

// ---------------------------------------------------------------------------
// Device scratch (allocations forbidden -> __device__ globals)
// ---------------------------------------------------------------------------
__device__ __align__(1024) __nv_bfloat16 g_h1_hi[(size_t)BATCH * HID];
__device__ __align__(1024) __nv_bfloat16 g_h1_lo[(size_t)BATCH * HID];
__device__ __align__(1024) __nv_bfloat16 g_w2_hi[(size_t)HID * HID];   // [K][N] same layout as W2
__device__ __align__(1024) __nv_bfloat16 g_w2_lo[(size_t)HID * HID];

// ---------------------------------------------------------------------------
// PTX helpers (arch-agnostic: sm_80+ features only)
// ---------------------------------------------------------------------------
__device__ __forceinline__ uint32_t smem_to_u32(const void* p) {
    uint32_t a;
    asm("{ .reg .u64 t; cvta.to.shared.u64 t, %1; cvt.u32.u64 %0, t; }" : "=r"(a) : "l"(p));
    return a;
}
__device__ __forceinline__ void ldsm4(uint32_t* r, uint32_t addr) {
    asm volatile("ldmatrix.sync.aligned.m8n8.x4.shared.b16 {%0,%1,%2,%3}, [%4];"
        : "=r"(r[0]), "=r"(r[1]), "=r"(r[2]), "=r"(r[3]) : "r"(addr));
}
__device__ __forceinline__ void ldsm4t(uint32_t* r, uint32_t addr) {
    asm volatile("ldmatrix.sync.aligned.m8n8.x4.trans.shared.b16 {%0,%1,%2,%3}, [%4];"
        : "=r"(r[0]), "=r"(r[1]), "=r"(r[2]), "=r"(r[3]) : "r"(addr));
}
__device__ __forceinline__ void mma16816(float* d, const uint32_t* a, const uint32_t* b) {
    asm volatile("mma.sync.aligned.m16n8k16.row.col.f32.bf16.bf16.f32 "
        "{%0,%1,%2,%3}, {%4,%5,%6,%7}, {%8,%9}, {%0,%1,%2,%3};"
        : "+f"(d[0]), "+f"(d[1]), "+f"(d[2]), "+f"(d[3])
        : "r"(a[0]), "r"(a[1]), "r"(a[2]), "r"(a[3]), "r"(b[0]), "r"(b[1]));
}
__device__ __forceinline__ void cpasync16(uint32_t dst, const void* src) {
    asm volatile("cp.async.cg.shared.global [%0], [%1], 16;" :: "r"(dst), "l"(src));
}
#define CP_COMMIT() asm volatile("cp.async.commit_group;" ::: "memory")
#define CP_WAIT1()  asm volatile("cp.async.wait_group 1;" ::: "memory")

// ---------------------------------------------------------------------------
// out[b] = bc[0]
// ---------------------------------------------------------------------------
__global__ void init_logits_kernel(const float* __restrict__ bc, float* __restrict__ out) {
    int i = blockIdx.x * 256 + threadIdx.x;
    out[i] = bc[0];
}

// ---------------------------------------------------------------------------
// W2 fp32 [K][N] -> bf16 hi/lo, same layout (elementwise)
// ---------------------------------------------------------------------------
__global__ void w2conv_kernel(const float* __restrict__ W2) {
    size_t i = ((size_t)blockIdx.x * 256 + threadIdx.x) * 4;
    float4 v = *(const float4*)(W2 + i);
    __nv_bfloat16 h0 = __float2bfloat16(v.x), h1 = __float2bfloat16(v.y);
    __nv_bfloat16 h2 = __float2bfloat16(v.z), h3 = __float2bfloat16(v.w);
    __nv_bfloat162* dhi = (__nv_bfloat162*)(g_w2_hi + i);
    __nv_bfloat162* dlo = (__nv_bfloat162*)(g_w2_lo + i);
    dhi[0] = __halves2bfloat162(h0, h1);
    dhi[1] = __halves2bfloat162(h2, h3);
    dlo[0] = __halves2bfloat162(__float2bfloat16(v.x - __bfloat162float(h0)),
                                __float2bfloat16(v.y - __bfloat162float(h1)));
    dlo[1] = __halves2bfloat162(__float2bfloat16(v.z - __bfloat162float(h2)),
                                __float2bfloat16(v.w - __bfloat162float(h3)));
}

// ---------------------------------------------------------------------------
// Layer 1 (closed-form quantum features), emits h1 as bf16 hi/lo
// ---------------------------------------------------------------------------
__global__ void layer1_kernel(const float* __restrict__ x,
                              const float* __restrict__ W1,
                              const float* __restrict__ b1) {
    int b = blockIdx.x;
    int k = threadIdx.x * 8;
    float x0 = x[2 * b], x1 = x[2 * b + 1];
    float c0 = cosf(x0), c01 = c0 * cosf(x1);

    float h[8];
    #pragma unroll
    for (int u = 0; u < 2; u++) {
        int kk = k + 4 * u;
        float4 w0 = *(const float4*)(W1 + 0 * HID + kk);
        float4 w1 = *(const float4*)(W1 + 1 * HID + kk);
        float4 w2 = *(const float4*)(W1 + 2 * HID + kk);
        float4 w3 = *(const float4*)(W1 + 3 * HID + kk);
        float4 w4 = *(const float4*)(W1 + 4 * HID + kk);
        float4 w5 = *(const float4*)(W1 + 5 * HID + kk);
        float4 bb = *(const float4*)(b1 + kk);
        h[4*u+0] = tanhf(x0 * w0.x + x1 * w1.x + c0 * w2.x + c01 * w3.x + w4.x + w5.x + bb.x);
        h[4*u+1] = tanhf(x0 * w0.y + x1 * w1.y + c0 * w2.y + c01 * w3.y + w4.y + w5.y + bb.y);
        h[4*u+2] = tanhf(x0 * w0.z + x1 * w1.z + c0 * w2.z + c01 * w3.z + w4.z + w5.z + bb.z);
        h[4*u+3] = tanhf(x0 * w0.w + x1 * w1.w + c0 * w2.w + c01 * w3.w + w4.w + w5.w + bb.w);
    }

    __nv_bfloat162* dhi = (__nv_bfloat162*)(g_h1_hi + (size_t)b * HID + k);
    __nv_bfloat162* dlo = (__nv_bfloat162*)(g_h1_lo + (size_t)b * HID + k);
    #pragma unroll
    for (int p = 0; p < 4; p++) {
        __nv_bfloat16 h0 = __float2bfloat16(h[2*p]);
        __nv_bfloat16 h1b = __float2bfloat16(h[2*p+1]);
        __nv_bfloat16 l0 = __float2bfloat16(h[2*p]   - __bfloat162float(h0));
        __nv_bfloat16 l1 = __float2bfloat16(h[2*p+1] - __bfloat162float(h1b));
        dhi[p] = __halves2bfloat162(h0, h1b);
        dlo[p] = __halves2bfloat162(l0, l1);
    }
}

// ---------------------------------------------------------------------------
// GEMM2 via mma.sync bf16, 3-split (hi*hi + hi*lo + lo*hi), fused epilogue:
//   h2 = tanh(h1 @ W2 + b2); out[m] += sum_n h2[m,n] * Wc[n]
// Tile 128x128x32, 256 threads (2x4 warps, 64x32 per warp), 3-stage cp.async.
// ---------------------------------------------------------------------------
#define BM 128
#define BN 128
#define BKQ 32
#define NIT (HID / BKQ)        // 64
#define LDA 40                 // 32 + 8 pad (bf16)
#define LDB 136                // 128 + 8 pad
#define A_BYTES (BM * LDA * 2)     // 10240
#define B_BYTES (BKQ * LDB * 2)    // 8704
#define ST_BYTES (2 * A_BYTES + 2 * B_BYTES)   // 37888
#define NSTAGE 3
#define GEMM_SMEM (NSTAGE * ST_BYTES)          // 113664

__global__ void __launch_bounds__(256, 1)
gemm2_mma_kernel(const float* __restrict__ b2,
                 const float* __restrict__ Wc,
                 float* __restrict__ out) {
    extern __shared__ __align__(16) char smem[];
    const int tid = threadIdx.x;
    const int lane = tid & 31;
    const int wid = tid >> 5;
    const int warp_m = wid >> 2;     // 0..1
    const int warp_n = wid & 3;      // 0..3
    const int row0 = blockIdx.y * BM;
    const int n0 = blockIdx.x * BN;
    const uint32_t smb = smem_to_u32(smem);

    float acc[4][4][4];
    #pragma unroll
    for (int mt = 0; mt < 4; mt++)
        #pragma unroll
        for (int nt = 0; nt < 4; nt++)
            #pragma unroll
            for (int e = 0; e < 4; e++)
                acc[mt][nt][e] = 0.f;

    // per-thread load indices (8 cp.async per stage)
    const int segA0 = tid, segA1 = tid + 256;

    // ---- prefetch stages 0,1 ----
    #pragma unroll
    for (int pre = 0; pre < 2; pre++) {
        const int k0 = pre * BKQ;
        const uint32_t st = smb + pre * ST_BYTES;
        #pragma unroll
        for (int l = 0; l < 2; l++) {
            int seg = (l == 0) ? segA0 : segA1;
            int r = seg >> 2, sc = (seg & 3) * 8;
            cpasync16(st + (r * LDA + sc) * 2,            g_h1_hi + (size_t)(row0 + r) * HID + k0 + sc);
            cpasync16(st + A_BYTES + (r * LDA + sc) * 2,  g_h1_lo + (size_t)(row0 + r) * HID + k0 + sc);
            int kr = seg >> 4, nc = (seg & 15) * 8;
            cpasync16(st + 2 * A_BYTES + (kr * LDB + nc) * 2,
                      g_w2_hi + (size_t)(k0 + kr) * HID + n0 + nc);
            cpasync16(st + 2 * A_BYTES + B_BYTES + (kr * LDB + nc) * 2,
                      g_w2_lo + (size_t)(k0 + kr) * HID + n0 + nc);
        }
        CP_COMMIT();
    }

    for (int it = 0; it < NIT; it++) {
        CP_WAIT1();
        __syncthreads();

        // prefetch stage it+2
        {
            const int pf = it + 2;
            const uint32_t st = smb + (pf % NSTAGE) * ST_BYTES;
            if (pf < NIT) {
                const int k0 = pf * BKQ;
                #pragma unroll
                for (int l = 0; l < 2; l++) {
                    int seg = (l == 0) ? segA0 : segA1;
                    int r = seg >> 2, sc = (seg & 3) * 8;
                    cpasync16(st + (r * LDA + sc) * 2,           g_h1_hi + (size_t)(row0 + r) * HID + k0 + sc);
                    cpasync16(st + A_BYTES + (r * LDA + sc) * 2, g_h1_lo + (size_t)(row0 + r) * HID + k0 + sc);
                    int kr = seg >> 4, nc = (seg & 15) * 8;
                    cpasync16(st + 2 * A_BYTES + (kr * LDB + nc) * 2,
                              g_w2_hi + (size_t)(k0 + kr) * HID + n0 + nc);
                    cpasync16(st + 2 * A_BYTES + B_BYTES + (kr * LDB + nc) * 2,
                              g_w2_lo + (size_t)(k0 + kr) * HID + n0 + nc);
                }
            }
            CP_COMMIT();
        }

        // ---- compute stage it ----
        const uint32_t st = smb + (it % NSTAGE) * ST_BYTES;
        const uint32_t aHiB = st, aLoB = st + A_BYTES;
        const uint32_t bHiB = st + 2 * A_BYTES, bLoB = bHiB + B_BYTES;

        #pragma unroll
        for (int ks = 0; ks < 2; ks++) {
            const int kof = ks * 16;
            uint32_t ah[4][4], al[4][4], bh[4][2], bl[4][2];
            #pragma unroll
            for (int mt = 0; mt < 4; mt++) {
                uint32_t off = ((warp_m * 64 + mt * 16 + (lane & 15)) * LDA
                                + kof + (lane >> 4) * 8) * 2;
                ldsm4(ah[mt], aHiB + off);
                ldsm4(al[mt], aLoB + off);
            }
            #pragma unroll
            for (int ng = 0; ng < 2; ng++) {
                uint32_t off = ((kof + (lane & 15)) * LDB
                                + warp_n * 32 + ng * 16 + (lane >> 4) * 8) * 2;
                uint32_t t[4];
                ldsm4t(t, bHiB + off);
                bh[2*ng][0] = t[0]; bh[2*ng][1] = t[1];
                bh[2*ng+1][0] = t[2]; bh[2*ng+1][1] = t[3];
                ldsm4t(t, bLoB + off);
                bl[2*ng][0] = t[0]; bl[2*ng][1] = t[1];
                bl[2*ng+1][0] = t[2]; bl[2*ng+1][1] = t[3];
            }
            #pragma unroll
            for (int mt = 0; mt < 4; mt++)
                #pragma unroll
                for (int nt = 0; nt < 4; nt++) {
                    mma16816(acc[mt][nt], ah[mt], bh[nt]);
                    mma16816(acc[mt][nt], ah[mt], bl[nt]);
                    mma16816(acc[mt][nt], al[mt], bh[nt]);
                }
        }
        __syncthreads();
    }

    // ---- fused epilogue: tanh + b2, dot with Wc, quad-reduce, atomicAdd ----
    const int r = lane >> 2, cq = lane & 3;
    #pragma unroll
    for (int mt = 0; mt < 4; mt++) {
        float p0 = 0.f, p1 = 0.f;
        #pragma unroll
        for (int nt = 0; nt < 4; nt++) {
            int c = n0 + warp_n * 32 + nt * 8 + cq * 2;
            float w0 = __ldg(Wc + c), w1 = __ldg(Wc + c + 1);
            float bb0 = __ldg(b2 + c), bb1 = __ldg(b2 + c + 1);
            p0 += tanhf(acc[mt][nt][0] + bb0) * w0 + tanhf(acc[mt][nt][1] + bb1) * w1;
            p1 += tanhf(acc[mt][nt][2] + bb0) * w0 + tanhf(acc[mt][nt][3] + bb1) * w1;
        }
        p0 += __shfl_xor_sync(0xffffffffu, p0, 1);
        p0 += __shfl_xor_sync(0xffffffffu, p0, 2);
        p1 += __shfl_xor_sync(0xffffffffu, p1, 1);
        p1 += __shfl_xor_sync(0xffffffffu, p1, 2);
        if (cq == 0) {
            int grow = row0 + warp_m * 64 + mt * 16 + r;
            atomicAdd(out + grow, p0);
            atomicAdd(out + grow + 8, p1);
        }
    }
}

// ---------------------------------------------------------------------------
// Risk head (2->8->4->1)
// ---------------------------------------------------------------------------
__global__ void risk_kernel(const float* __restrict__ x,
                            const float* __restrict__ Wr1, const float* __restrict__ br1,
                            const float* __restrict__ Wr2, const float* __restrict__ br2,
                            const float* __restrict__ Wr3, const float* __restrict__ br3,
                            float* __restrict__ out) {
    int b = blockIdx.x * 256 + threadIdx.x;
    float x0 = x[2 * b], x1 = x[2 * b + 1];
    float r1[8];
    #pragma unroll
    for (int j = 0; j < 8; j++)
        r1[j] = tanhf(x0 * Wr1[j] + x1 * Wr1[8 + j] + br1[j]);
    float r2[4];
    #pragma unroll
    for (int m = 0; m < 4; m++) {
        float s = br2[m];
        #pragma unroll
        for (int j = 0; j < 8; j++) s += r1[j] * Wr2[j * 4 + m];
        r2[m] = tanhf(s);
    }
    float risk = br3[0];
    #pragma unroll
    for (int m = 0; m < 4; m++) risk += r2[m] * Wr3[m];
    out[BATCH + b] = risk;
}

// ---------------------------------------------------------------------------
extern "C" void kernel_launch(void* const* d_in, const int* in_sizes, int n_in,
                              void* d_out, int out_size) {
    const float* x   = (const float*)d_in[0];
    const float* W1  = (const float*)d_in[1];
    const float* b1  = (const float*)d_in[2];
    const float* W2  = (const float*)d_in[3];
    const float* b2  = (const float*)d_in[4];
    const float* Wc  = (const float*)d_in[5];
    const float* bc  = (const float*)d_in[6];
    const float* Wr1 = (const float*)d_in[7];
    const float* br1 = (const float*)d_in[8];
    const float* Wr2 = (const float*)d_in[9];
    const float* br2 = (const float*)d_in[10];
    const float* Wr3 = (const float*)d_in[11];
    const float* br3 = (const float*)d_in[12];
    float* out = (float*)d_out;

    static bool attr_set = false;
    if (!attr_set) {
        cudaFuncSetAttribute(gemm2_mma_kernel,
                             cudaFuncAttributeMaxDynamicSharedMemorySize, GEMM_SMEM);
        attr_set = true;
    }

    init_logits_kernel<<<BATCH / 256, 256>>>(bc, out);
    w2conv_kernel<<<(HID * HID) / 1024, 256>>>(W2);
    layer1_kernel<<<BATCH, 256>>>(x, W1, b1);
    // blockIdx.x = n-tile (fastest) so the 16 CTAs sharing an A tile are adjacent
    gemm2_mma_kernel<<<dim3(HID / BN, BATCH / BM), 256, GEMM_SMEM>>>(b2, Wc, out);
    risk_kernel<<<BATCH / 256, 256>>>(x, Wr1, br1, Wr2, br2, Wr3, br3, out);
}

// round 5
// speedup vs baseline: 2.3784x; 1.0167x over previous
#include <cuda_runtime.h>
#include <cuda_bf16.h>
#include <math.h>
#include <stdint.h>

#define BATCH 32768
#define HID   2048

// ---------------------------------------------------------------------------
// Device scratch (allocations forbidden -> __device__ globals)
// ---------------------------------------------------------------------------
__device__ __align__(1024) __nv_bfloat16 g_h1_hi[(size_t)BATCH * HID];
__device__ __align__(1024) __nv_bfloat16 g_h1_lo[(size_t)BATCH * HID];
__device__ __align__(1024) __nv_bfloat16 g_w2_hi[(size_t)HID * HID];   // [K][N] same layout as W2
__device__ __align__(1024) __nv_bfloat16 g_w2_lo[(size_t)HID * HID];

// ---------------------------------------------------------------------------
// PTX helpers (arch-agnostic: sm_80+ features only)
// ---------------------------------------------------------------------------
__device__ __forceinline__ uint32_t smem_to_u32(const void* p) {
    uint32_t a;
    asm("{ .reg .u64 t; cvta.to.shared.u64 t, %1; cvt.u32.u64 %0, t; }" : "=r"(a) : "l"(p));
    return a;
}
__device__ __forceinline__ void ldsm4(uint32_t* r, uint32_t addr) {
    asm volatile("ldmatrix.sync.aligned.m8n8.x4.shared.b16 {%0,%1,%2,%3}, [%4];"
        : "=r"(r[0]), "=r"(r[1]), "=r"(r[2]), "=r"(r[3]) : "r"(addr));
}
__device__ __forceinline__ void ldsm4t(uint32_t* r, uint32_t addr) {
    asm volatile("ldmatrix.sync.aligned.m8n8.x4.trans.shared.b16 {%0,%1,%2,%3}, [%4];"
        : "=r"(r[0]), "=r"(r[1]), "=r"(r[2]), "=r"(r[3]) : "r"(addr));
}
__device__ __forceinline__ void mma16816(float* d, const uint32_t* a, const uint32_t* b) {
    asm volatile("mma.sync.aligned.m16n8k16.row.col.f32.bf16.bf16.f32 "
        "{%0,%1,%2,%3}, {%4,%5,%6,%7}, {%8,%9}, {%0,%1,%2,%3};"
        : "+f"(d[0]), "+f"(d[1]), "+f"(d[2]), "+f"(d[3])
        : "r"(a[0]), "r"(a[1]), "r"(a[2]), "r"(a[3]), "r"(b[0]), "r"(b[1]));
}
__device__ __forceinline__ void cpasync16(uint32_t dst, const void* src) {
    asm volatile("cp.async.cg.shared.global [%0], [%1], 16;" :: "r"(dst), "l"(src));
}
#define CP_COMMIT() asm volatile("cp.async.commit_group;" ::: "memory")
#define CP_WAIT1()  asm volatile("cp.async.wait_group 1;" ::: "memory")

// ---------------------------------------------------------------------------
// out[b] = bc[0]
// ---------------------------------------------------------------------------
__global__ void init_logits_kernel(const float* __restrict__ bc, float* __restrict__ out) {
    int i = blockIdx.x * 256 + threadIdx.x;
    out[i] = bc[0];
}

// ---------------------------------------------------------------------------
// W2 fp32 [K][N] -> bf16 hi/lo, same layout (elementwise)
// ---------------------------------------------------------------------------
__global__ void w2conv_kernel(const float* __restrict__ W2) {
    size_t i = ((size_t)blockIdx.x * 256 + threadIdx.x) * 4;
    float4 v = *(const float4*)(W2 + i);
    __nv_bfloat16 h0 = __float2bfloat16(v.x), h1 = __float2bfloat16(v.y);
    __nv_bfloat16 h2 = __float2bfloat16(v.z), h3 = __float2bfloat16(v.w);
    __nv_bfloat162* dhi = (__nv_bfloat162*)(g_w2_hi + i);
    __nv_bfloat162* dlo = (__nv_bfloat162*)(g_w2_lo + i);
    dhi[0] = __halves2bfloat162(h0, h1);
    dhi[1] = __halves2bfloat162(h2, h3);
    dlo[0] = __halves2bfloat162(__float2bfloat16(v.x - __bfloat162float(h0)),
                                __float2bfloat16(v.y - __bfloat162float(h1)));
    dlo[1] = __halves2bfloat162(__float2bfloat16(v.z - __bfloat162float(h2)),
                                __float2bfloat16(v.w - __bfloat162float(h3)));
}

// ---------------------------------------------------------------------------
// Layer 1 (closed-form quantum features), 8 batch rows per block,
// W1 slice register-resident (cuts W1 L2 traffic 8x).
// ---------------------------------------------------------------------------
#define L1_ROWS 8
__global__ void __launch_bounds__(256)
layer1_kernel(const float* __restrict__ x,
              const float* __restrict__ W1,
              const float* __restrict__ b1) {
    const int b0 = blockIdx.x * L1_ROWS;
    const int k = threadIdx.x * 8;

    __shared__ float xs[2 * L1_ROWS];
    if (threadIdx.x < 2 * L1_ROWS) xs[threadIdx.x] = x[2 * b0 + threadIdx.x];

    // register-resident W1 slice for this thread's 8 columns
    float4 w0a = *(const float4*)(W1 + 0 * HID + k), w0b = *(const float4*)(W1 + 0 * HID + k + 4);
    float4 w1a = *(const float4*)(W1 + 1 * HID + k), w1b = *(const float4*)(W1 + 1 * HID + k + 4);
    float4 w2a = *(const float4*)(W1 + 2 * HID + k), w2b = *(const float4*)(W1 + 2 * HID + k + 4);
    float4 w3a = *(const float4*)(W1 + 3 * HID + k), w3b = *(const float4*)(W1 + 3 * HID + k + 4);
    float4 w4a = *(const float4*)(W1 + 4 * HID + k), w4b = *(const float4*)(W1 + 4 * HID + k + 4);
    float4 w5a = *(const float4*)(W1 + 5 * HID + k), w5b = *(const float4*)(W1 + 5 * HID + k + 4);
    float4 bba = *(const float4*)(b1 + k),           bbb = *(const float4*)(b1 + k + 4);
    // fold constant terms: cc = W1[4] + W1[5] + b1
    float cc[8] = { w4a.x + w5a.x + bba.x, w4a.y + w5a.y + bba.y,
                    w4a.z + w5a.z + bba.z, w4a.w + w5a.w + bba.w,
                    w4b.x + w5b.x + bbb.x, w4b.y + w5b.y + bbb.y,
                    w4b.z + w5b.z + bbb.z, w4b.w + w5b.w + bbb.w };
    float wa[8] = { w0a.x, w0a.y, w0a.z, w0a.w, w0b.x, w0b.y, w0b.z, w0b.w };
    float wb[8] = { w1a.x, w1a.y, w1a.z, w1a.w, w1b.x, w1b.y, w1b.z, w1b.w };
    float wq0[8] = { w2a.x, w2a.y, w2a.z, w2a.w, w2b.x, w2b.y, w2b.z, w2b.w };
    float wq1[8] = { w3a.x, w3a.y, w3a.z, w3a.w, w3b.x, w3b.y, w3b.z, w3b.w };
    __syncthreads();

    #pragma unroll
    for (int r = 0; r < L1_ROWS; r++) {
        float x0 = xs[2 * r], x1 = xs[2 * r + 1];
        float c0 = cosf(x0), c01 = c0 * cosf(x1);
        __nv_bfloat162 hi[4], lo[4];
        #pragma unroll
        for (int p = 0; p < 4; p++) {
            float v0 = tanhf(x0 * wa[2*p]   + x1 * wb[2*p]   + c0 * wq0[2*p]   + c01 * wq1[2*p]   + cc[2*p]);
            float v1 = tanhf(x0 * wa[2*p+1] + x1 * wb[2*p+1] + c0 * wq0[2*p+1] + c01 * wq1[2*p+1] + cc[2*p+1]);
            __nv_bfloat16 h0 = __float2bfloat16(v0);
            __nv_bfloat16 h1b = __float2bfloat16(v1);
            hi[p] = __halves2bfloat162(h0, h1b);
            lo[p] = __halves2bfloat162(__float2bfloat16(v0 - __bfloat162float(h0)),
                                       __float2bfloat16(v1 - __bfloat162float(h1b)));
        }
        *(uint4*)(g_h1_hi + (size_t)(b0 + r) * HID + k) = *(uint4*)hi;
        *(uint4*)(g_h1_lo + (size_t)(b0 + r) * HID + k) = *(uint4*)lo;
    }
}

// ---------------------------------------------------------------------------
// GEMM2 via mma.sync bf16, 3-split (hi*hi + hi*lo + lo*hi), fused epilogue:
//   h2 = tanh(h1 @ W2 + b2); out[m] += sum_n h2[m,n] * Wc[n]
// Tile 128x128x32, 256 threads (2x4 warps, 64x32 per warp), 3-stage cp.async.
// Splits issued as 3 separate passes over 16 accumulators -> no acc RAW chains.
// ---------------------------------------------------------------------------
#define BM 128
#define BN 128
#define BKQ 32
#define NIT (HID / BKQ)        // 64
#define LDA 40                 // 32 + 8 pad (bf16)
#define LDB 136                // 128 + 8 pad
#define A_BYTES (BM * LDA * 2)     // 10240
#define B_BYTES (BKQ * LDB * 2)    // 8704
#define ST_BYTES (2 * A_BYTES + 2 * B_BYTES)   // 37888
#define NSTAGE 3
#define GEMM_SMEM (NSTAGE * ST_BYTES)          // 113664

__global__ void __launch_bounds__(256, 1)
gemm2_mma_kernel(const float* __restrict__ b2,
                 const float* __restrict__ Wc,
                 float* __restrict__ out) {
    extern __shared__ __align__(16) char smem[];
    const int tid = threadIdx.x;
    const int lane = tid & 31;
    const int wid = tid >> 5;
    const int warp_m = wid >> 2;     // 0..1
    const int warp_n = wid & 3;      // 0..3
    const int row0 = blockIdx.y * BM;
    const int n0 = blockIdx.x * BN;
    const uint32_t smb = smem_to_u32(smem);

    float acc[4][4][4];
    #pragma unroll
    for (int mt = 0; mt < 4; mt++)
        #pragma unroll
        for (int nt = 0; nt < 4; nt++)
            #pragma unroll
            for (int e = 0; e < 4; e++)
                acc[mt][nt][e] = 0.f;

    const int segA0 = tid, segA1 = tid + 256;

    // ---- prefetch stages 0,1 ----
    #pragma unroll
    for (int pre = 0; pre < 2; pre++) {
        const int k0 = pre * BKQ;
        const uint32_t st = smb + pre * ST_BYTES;
        #pragma unroll
        for (int l = 0; l < 2; l++) {
            int seg = (l == 0) ? segA0 : segA1;
            int r = seg >> 2, sc = (seg & 3) * 8;
            cpasync16(st + (r * LDA + sc) * 2,            g_h1_hi + (size_t)(row0 + r) * HID + k0 + sc);
            cpasync16(st + A_BYTES + (r * LDA + sc) * 2,  g_h1_lo + (size_t)(row0 + r) * HID + k0 + sc);
            int kr = seg >> 4, nc = (seg & 15) * 8;
            cpasync16(st + 2 * A_BYTES + (kr * LDB + nc) * 2,
                      g_w2_hi + (size_t)(k0 + kr) * HID + n0 + nc);
            cpasync16(st + 2 * A_BYTES + B_BYTES + (kr * LDB + nc) * 2,
                      g_w2_lo + (size_t)(k0 + kr) * HID + n0 + nc);
        }
        CP_COMMIT();
    }

    for (int it = 0; it < NIT; it++) {
        CP_WAIT1();
        __syncthreads();

        // prefetch stage it+2
        {
            const int pf = it + 2;
            const uint32_t st = smb + (pf % NSTAGE) * ST_BYTES;
            if (pf < NIT) {
                const int k0 = pf * BKQ;
                #pragma unroll
                for (int l = 0; l < 2; l++) {
                    int seg = (l == 0) ? segA0 : segA1;
                    int r = seg >> 2, sc = (seg & 3) * 8;
                    cpasync16(st + (r * LDA + sc) * 2,           g_h1_hi + (size_t)(row0 + r) * HID + k0 + sc);
                    cpasync16(st + A_BYTES + (r * LDA + sc) * 2, g_h1_lo + (size_t)(row0 + r) * HID + k0 + sc);
                    int kr = seg >> 4, nc = (seg & 15) * 8;
                    cpasync16(st + 2 * A_BYTES + (kr * LDB + nc) * 2,
                              g_w2_hi + (size_t)(k0 + kr) * HID + n0 + nc);
                    cpasync16(st + 2 * A_BYTES + B_BYTES + (kr * LDB + nc) * 2,
                              g_w2_lo + (size_t)(k0 + kr) * HID + n0 + nc);
                }
            }
            CP_COMMIT();
        }

        // ---- compute stage it ----
        const uint32_t st = smb + (it % NSTAGE) * ST_BYTES;
        const uint32_t aHiB = st, aLoB = st + A_BYTES;
        const uint32_t bHiB = st + 2 * A_BYTES, bLoB = bHiB + B_BYTES;

        #pragma unroll
        for (int ks = 0; ks < 2; ks++) {
            const int kof = ks * 16;
            uint32_t ah[4][4], al[4][4], bh[4][2], bl[4][2];
            #pragma unroll
            for (int mt = 0; mt < 4; mt++) {
                uint32_t off = ((warp_m * 64 + mt * 16 + (lane & 15)) * LDA
                                + kof + (lane >> 4) * 8) * 2;
                ldsm4(ah[mt], aHiB + off);
                ldsm4(al[mt], aLoB + off);
            }
            #pragma unroll
            for (int ng = 0; ng < 2; ng++) {
                uint32_t off = ((kof + (lane & 15)) * LDB
                                + warp_n * 32 + ng * 16 + (lane >> 4) * 8) * 2;
                uint32_t t[4];
                ldsm4t(t, bHiB + off);
                bh[2*ng][0] = t[0]; bh[2*ng][1] = t[1];
                bh[2*ng+1][0] = t[2]; bh[2*ng+1][1] = t[3];
                ldsm4t(t, bLoB + off);
                bl[2*ng][0] = t[0]; bl[2*ng][1] = t[1];
                bl[2*ng+1][0] = t[2]; bl[2*ng+1][1] = t[3];
            }
            // Pass 1: hi*hi — 16 independent accumulators
            #pragma unroll
            for (int mt = 0; mt < 4; mt++)
                #pragma unroll
                for (int nt = 0; nt < 4; nt++)
                    mma16816(acc[mt][nt], ah[mt], bh[nt]);
            // Pass 2: hi*lo
            #pragma unroll
            for (int mt = 0; mt < 4; mt++)
                #pragma unroll
                for (int nt = 0; nt < 4; nt++)
                    mma16816(acc[mt][nt], ah[mt], bl[nt]);
            // Pass 3: lo*hi
            #pragma unroll
            for (int mt = 0; mt < 4; mt++)
                #pragma unroll
                for (int nt = 0; nt < 4; nt++)
                    mma16816(acc[mt][nt], al[mt], bh[nt]);
        }
        __syncthreads();
    }

    // ---- fused epilogue: tanh + b2, dot with Wc, quad-reduce, atomicAdd ----
    const int r = lane >> 2, cq = lane & 3;
    #pragma unroll
    for (int mt = 0; mt < 4; mt++) {
        float p0 = 0.f, p1 = 0.f;
        #pragma unroll
        for (int nt = 0; nt < 4; nt++) {
            int c = n0 + warp_n * 32 + nt * 8 + cq * 2;
            float w0 = __ldg(Wc + c), w1 = __ldg(Wc + c + 1);
            float bb0 = __ldg(b2 + c), bb1 = __ldg(b2 + c + 1);
            p0 += tanhf(acc[mt][nt][0] + bb0) * w0 + tanhf(acc[mt][nt][1] + bb1) * w1;
            p1 += tanhf(acc[mt][nt][2] + bb0) * w0 + tanhf(acc[mt][nt][3] + bb1) * w1;
        }
        p0 += __shfl_xor_sync(0xffffffffu, p0, 1);
        p0 += __shfl_xor_sync(0xffffffffu, p0, 2);
        p1 += __shfl_xor_sync(0xffffffffu, p1, 1);
        p1 += __shfl_xor_sync(0xffffffffu, p1, 2);
        if (cq == 0) {
            int grow = row0 + warp_m * 64 + mt * 16 + r;
            atomicAdd(out + grow, p0);
            atomicAdd(out + grow + 8, p1);
        }
    }
}

// ---------------------------------------------------------------------------
// Risk head (2->8->4->1)
// ---------------------------------------------------------------------------
__global__ void risk_kernel(const float* __restrict__ x,
                            const float* __restrict__ Wr1, const float* __restrict__ br1,
                            const float* __restrict__ Wr2, const float* __restrict__ br2,
                            const float* __restrict__ Wr3, const float* __restrict__ br3,
                            float* __restrict__ out) {
    int b = blockIdx.x * 256 + threadIdx.x;
    float x0 = x[2 * b], x1 = x[2 * b + 1];
    float r1[8];
    #pragma unroll
    for (int j = 0; j < 8; j++)
        r1[j] = tanhf(x0 * Wr1[j] + x1 * Wr1[8 + j] + br1[j]);
    float r2[4];
    #pragma unroll
    for (int m = 0; m < 4; m++) {
        float s = br2[m];
        #pragma unroll
        for (int j = 0; j < 8; j++) s += r1[j] * Wr2[j * 4 + m];
        r2[m] = tanhf(s);
    }
    float risk = br3[0];
    #pragma unroll
    for (int m = 0; m < 4; m++) risk += r2[m] * Wr3[m];
    out[BATCH + b] = risk;
}

// ---------------------------------------------------------------------------
extern "C" void kernel_launch(void* const* d_in, const int* in_sizes, int n_in,
                              void* d_out, int out_size) {
    const float* x   = (const float*)d_in[0];
    const float* W1  = (const float*)d_in[1];
    const float* b1  = (const float*)d_in[2];
    const float* W2  = (const float*)d_in[3];
    const float* b2  = (const float*)d_in[4];
    const float* Wc  = (const float*)d_in[5];
    const float* bc  = (const float*)d_in[6];
    const float* Wr1 = (const float*)d_in[7];
    const float* br1 = (const float*)d_in[8];
    const float* Wr2 = (const float*)d_in[9];
    const float* br2 = (const float*)d_in[10];
    const float* Wr3 = (const float*)d_in[11];
    const float* br3 = (const float*)d_in[12];
    float* out = (float*)d_out;

    static bool attr_set = false;
    if (!attr_set) {
        cudaFuncSetAttribute(gemm2_mma_kernel,
                             cudaFuncAttributeMaxDynamicSharedMemorySize, GEMM_SMEM);
        attr_set = true;
    }

    init_logits_kernel<<<BATCH / 256, 256>>>(bc, out);
    w2conv_kernel<<<(HID * HID) / 1024, 256>>>(W2);
    layer1_kernel<<<BATCH / L1_ROWS, 256>>>(x, W1, b1);
    // blockIdx.x = n-tile (fastest) so the 16 CTAs sharing an A tile are adjacent
    gemm2_mma_kernel<<<dim3(HID / BN, BATCH / BM), 256, GEMM_SMEM>>>(b2, Wc, out);
    risk_kernel<<<BATCH / 256, 256>>>(x, Wr1, br1, Wr2, br2, Wr3, br3, out);
}

// round 6
// speedup vs baseline: 6.9680x; 2.9298x over previous
#include <cuda_runtime.h>
#include <cuda_fp16.h>
#include <math.h>
#include <stdint.h>

#define BATCH 32768
#define HID   2048

// ---------------------------------------------------------------------------
// Device scratch (allocations forbidden -> __device__ globals)
// ---------------------------------------------------------------------------
__device__ __align__(1024) __half g_h1[(size_t)BATCH * HID];
__device__ __align__(1024) __half g_w2[(size_t)HID * HID];   // [K][N] same layout as W2

// ---------------------------------------------------------------------------
// PTX helpers (arch-agnostic: sm_80+ features only)
// ---------------------------------------------------------------------------
__device__ __forceinline__ uint32_t smem_to_u32(const void* p) {
    uint32_t a;
    asm("{ .reg .u64 t; cvta.to.shared.u64 t, %1; cvt.u32.u64 %0, t; }" : "=r"(a) : "l"(p));
    return a;
}
__device__ __forceinline__ void ldsm4(uint32_t* r, uint32_t addr) {
    asm volatile("ldmatrix.sync.aligned.m8n8.x4.shared.b16 {%0,%1,%2,%3}, [%4];"
        : "=r"(r[0]), "=r"(r[1]), "=r"(r[2]), "=r"(r[3]) : "r"(addr));
}
__device__ __forceinline__ void ldsm4t(uint32_t* r, uint32_t addr) {
    asm volatile("ldmatrix.sync.aligned.m8n8.x4.trans.shared.b16 {%0,%1,%2,%3}, [%4];"
        : "=r"(r[0]), "=r"(r[1]), "=r"(r[2]), "=r"(r[3]) : "r"(addr));
}
__device__ __forceinline__ void mma16816(float* d, const uint32_t* a, const uint32_t* b) {
    asm volatile("mma.sync.aligned.m16n8k16.row.col.f32.f16.f16.f32 "
        "{%0,%1,%2,%3}, {%4,%5,%6,%7}, {%8,%9}, {%0,%1,%2,%3};"
        : "+f"(d[0]), "+f"(d[1]), "+f"(d[2]), "+f"(d[3])
        : "r"(a[0]), "r"(a[1]), "r"(a[2]), "r"(a[3]), "r"(b[0]), "r"(b[1]));
}
__device__ __forceinline__ void cpasync16(uint32_t dst, const void* src) {
    asm volatile("cp.async.cg.shared.global [%0], [%1], 16;" :: "r"(dst), "l"(src));
}
#define CP_COMMIT() asm volatile("cp.async.commit_group;" ::: "memory")
#define CP_WAIT1()  asm volatile("cp.async.wait_group 1;" ::: "memory")

// ---------------------------------------------------------------------------
// out[b] = bc[0]
// ---------------------------------------------------------------------------
__global__ void init_logits_kernel(const float* __restrict__ bc, float* __restrict__ out) {
    int i = blockIdx.x * 256 + threadIdx.x;
    out[i] = bc[0];
}

// ---------------------------------------------------------------------------
// W2 fp32 [K][N] -> fp16, same layout (elementwise)
// ---------------------------------------------------------------------------
__global__ void w2conv_kernel(const float* __restrict__ W2) {
    size_t i = ((size_t)blockIdx.x * 256 + threadIdx.x) * 4;
    float4 v = *(const float4*)(W2 + i);
    __half2* d = (__half2*)(g_w2 + i);
    d[0] = __floats2half2_rn(v.x, v.y);
    d[1] = __floats2half2_rn(v.z, v.w);
}

// ---------------------------------------------------------------------------
// Layer 1 (closed-form quantum features), 8 batch rows per block,
// W1 slice register-resident. Emits fp16 h1.
// ---------------------------------------------------------------------------
#define L1_ROWS 8
__global__ void __launch_bounds__(256)
layer1_kernel(const float* __restrict__ x,
              const float* __restrict__ W1,
              const float* __restrict__ b1) {
    const int b0 = blockIdx.x * L1_ROWS;
    const int k = threadIdx.x * 8;

    __shared__ float xs[2 * L1_ROWS];
    if (threadIdx.x < 2 * L1_ROWS) xs[threadIdx.x] = x[2 * b0 + threadIdx.x];

    float4 w0a = *(const float4*)(W1 + 0 * HID + k), w0b = *(const float4*)(W1 + 0 * HID + k + 4);
    float4 w1a = *(const float4*)(W1 + 1 * HID + k), w1b = *(const float4*)(W1 + 1 * HID + k + 4);
    float4 w2a = *(const float4*)(W1 + 2 * HID + k), w2b = *(const float4*)(W1 + 2 * HID + k + 4);
    float4 w3a = *(const float4*)(W1 + 3 * HID + k), w3b = *(const float4*)(W1 + 3 * HID + k + 4);
    float4 w4a = *(const float4*)(W1 + 4 * HID + k), w4b = *(const float4*)(W1 + 4 * HID + k + 4);
    float4 w5a = *(const float4*)(W1 + 5 * HID + k), w5b = *(const float4*)(W1 + 5 * HID + k + 4);
    float4 bba = *(const float4*)(b1 + k),           bbb = *(const float4*)(b1 + k + 4);
    float cc[8] = { w4a.x + w5a.x + bba.x, w4a.y + w5a.y + bba.y,
                    w4a.z + w5a.z + bba.z, w4a.w + w5a.w + bba.w,
                    w4b.x + w5b.x + bbb.x, w4b.y + w5b.y + bbb.y,
                    w4b.z + w5b.z + bbb.z, w4b.w + w5b.w + bbb.w };
    float wa[8]  = { w0a.x, w0a.y, w0a.z, w0a.w, w0b.x, w0b.y, w0b.z, w0b.w };
    float wb[8]  = { w1a.x, w1a.y, w1a.z, w1a.w, w1b.x, w1b.y, w1b.z, w1b.w };
    float wq0[8] = { w2a.x, w2a.y, w2a.z, w2a.w, w2b.x, w2b.y, w2b.z, w2b.w };
    float wq1[8] = { w3a.x, w3a.y, w3a.z, w3a.w, w3b.x, w3b.y, w3b.z, w3b.w };
    __syncthreads();

    #pragma unroll
    for (int r = 0; r < L1_ROWS; r++) {
        float x0 = xs[2 * r], x1 = xs[2 * r + 1];
        float c0 = cosf(x0), c01 = c0 * cosf(x1);
        __half2 hv[4];
        #pragma unroll
        for (int p = 0; p < 4; p++) {
            float v0 = tanhf(x0 * wa[2*p]   + x1 * wb[2*p]   + c0 * wq0[2*p]   + c01 * wq1[2*p]   + cc[2*p]);
            float v1 = tanhf(x0 * wa[2*p+1] + x1 * wb[2*p+1] + c0 * wq0[2*p+1] + c01 * wq1[2*p+1] + cc[2*p+1]);
            hv[p] = __floats2half2_rn(v0, v1);
        }
        *(uint4*)(g_h1 + (size_t)(b0 + r) * HID + k) = *(uint4*)hv;
    }
}

// ---------------------------------------------------------------------------
// GEMM2 via mma.sync fp16 single-pass, fused epilogue:
//   h2 = tanh(h1 @ W2 + b2); out[m] += sum_n h2[m,n] * Wc[n]
// Tile 128x128x32, 256 threads (2x4 warps, 64x32 per warp), 3-stage cp.async,
// one barrier per iteration, 2 CTAs/SM.
// ---------------------------------------------------------------------------
#define BM 128
#define BN 128
#define BKQ 32
#define NIT (HID / BKQ)        // 64
#define LDA 40                 // 32 + 8 pad (fp16 elements)
#define LDB 136                // 128 + 8 pad
#define A_BYTES (BM * LDA * 2)     // 10240
#define B_BYTES (BKQ * LDB * 2)    // 8704
#define ST_BYTES (A_BYTES + B_BYTES)           // 18944
#define NSTAGE 3
#define GEMM_SMEM (NSTAGE * ST_BYTES)          // 56832

__global__ void __launch_bounds__(256, 2)
gemm2_mma_kernel(const float* __restrict__ b2,
                 const float* __restrict__ Wc,
                 float* __restrict__ out) {
    extern __shared__ __align__(16) char smem[];
    const int tid = threadIdx.x;
    const int lane = tid & 31;
    const int wid = tid >> 5;
    const int warp_m = wid >> 2;     // 0..1
    const int warp_n = wid & 3;      // 0..3
    const int row0 = blockIdx.y * BM;
    const int n0 = blockIdx.x * BN;
    const uint32_t smb = smem_to_u32(smem);

    float acc[4][4][4];
    #pragma unroll
    for (int mt = 0; mt < 4; mt++)
        #pragma unroll
        for (int nt = 0; nt < 4; nt++)
            #pragma unroll
            for (int e = 0; e < 4; e++)
                acc[mt][nt][e] = 0.f;

    // per-thread cp.async segments: A 512 segs, B 512 segs; 2 of each per thread
    // A seg: r = seg>>2 (row), sc = (seg&3)*8 (k elems)
    // B seg: kr = seg>>4 (k row), nc = (seg&15)*8 (n elems)

    // ---- prefetch stages 0,1 ----
    #pragma unroll
    for (int pre = 0; pre < 2; pre++) {
        const int k0 = pre * BKQ;
        const uint32_t st = smb + pre * ST_BYTES;
        #pragma unroll
        for (int l = 0; l < 2; l++) {
            int seg = tid + l * 256;
            int r = seg >> 2, sc = (seg & 3) * 8;
            cpasync16(st + (r * LDA + sc) * 2, g_h1 + (size_t)(row0 + r) * HID + k0 + sc);
            int kr = seg >> 4, nc = (seg & 15) * 8;
            cpasync16(st + A_BYTES + (kr * LDB + nc) * 2,
                      g_w2 + (size_t)(k0 + kr) * HID + n0 + nc);
        }
        CP_COMMIT();
    }

    for (int it = 0; it < NIT; it++) {
        CP_WAIT1();
        __syncthreads();   // stage `it` visible to all; all warps done with stage (it-1)%3

        // prefetch stage it+2 (writes buffer (it+2)%3 == (it-1)%3 -> safe after barrier)
        {
            const int pf = it + 2;
            if (pf < NIT) {
                const uint32_t st = smb + (pf % NSTAGE) * ST_BYTES;
                const int k0 = pf * BKQ;
                #pragma unroll
                for (int l = 0; l < 2; l++) {
                    int seg = tid + l * 256;
                    int r = seg >> 2, sc = (seg & 3) * 8;
                    cpasync16(st + (r * LDA + sc) * 2, g_h1 + (size_t)(row0 + r) * HID + k0 + sc);
                    int kr = seg >> 4, nc = (seg & 15) * 8;
                    cpasync16(st + A_BYTES + (kr * LDB + nc) * 2,
                              g_w2 + (size_t)(k0 + kr) * HID + n0 + nc);
                }
            }
            CP_COMMIT();
        }

        // ---- compute stage it ----
        const uint32_t st = smb + (it % NSTAGE) * ST_BYTES;
        const uint32_t aB = st, bB = st + A_BYTES;

        #pragma unroll
        for (int ks = 0; ks < 2; ks++) {
            const int kof = ks * 16;
            uint32_t a[4][4], b[4][2];
            #pragma unroll
            for (int mt = 0; mt < 4; mt++) {
                uint32_t off = ((warp_m * 64 + mt * 16 + (lane & 15)) * LDA
                                + kof + (lane >> 4) * 8) * 2;
                ldsm4(a[mt], aB + off);
            }
            #pragma unroll
            for (int ng = 0; ng < 2; ng++) {
                uint32_t off = ((kof + (lane & 15)) * LDB
                                + warp_n * 32 + ng * 16 + (lane >> 4) * 8) * 2;
                uint32_t t[4];
                ldsm4t(t, bB + off);
                b[2*ng][0] = t[0]; b[2*ng][1] = t[1];
                b[2*ng+1][0] = t[2]; b[2*ng+1][1] = t[3];
            }
            #pragma unroll
            for (int mt = 0; mt < 4; mt++)
                #pragma unroll
                for (int nt = 0; nt < 4; nt++)
                    mma16816(acc[mt][nt], a[mt], b[nt]);
        }
        // no end-of-loop barrier: 3-stage ring + top barrier protects reuse
    }

    // ---- fused epilogue: tanh + b2, dot with Wc, quad-reduce, atomicAdd ----
    const int r = lane >> 2, cq = lane & 3;
    #pragma unroll
    for (int mt = 0; mt < 4; mt++) {
        float p0 = 0.f, p1 = 0.f;
        #pragma unroll
        for (int nt = 0; nt < 4; nt++) {
            int c = n0 + warp_n * 32 + nt * 8 + cq * 2;
            float w0 = __ldg(Wc + c), w1 = __ldg(Wc + c + 1);
            float bb0 = __ldg(b2 + c), bb1 = __ldg(b2 + c + 1);
            p0 += tanhf(acc[mt][nt][0] + bb0) * w0 + tanhf(acc[mt][nt][1] + bb1) * w1;
            p1 += tanhf(acc[mt][nt][2] + bb0) * w0 + tanhf(acc[mt][nt][3] + bb1) * w1;
        }
        p0 += __shfl_xor_sync(0xffffffffu, p0, 1);
        p0 += __shfl_xor_sync(0xffffffffu, p0, 2);
        p1 += __shfl_xor_sync(0xffffffffu, p1, 1);
        p1 += __shfl_xor_sync(0xffffffffu, p1, 2);
        if (cq == 0) {
            int grow = row0 + warp_m * 64 + mt * 16 + r;
            atomicAdd(out + grow, p0);
            atomicAdd(out + grow + 8, p1);
        }
    }
}

// ---------------------------------------------------------------------------
// Risk head (2->8->4->1)
// ---------------------------------------------------------------------------
__global__ void risk_kernel(const float* __restrict__ x,
                            const float* __restrict__ Wr1, const float* __restrict__ br1,
                            const float* __restrict__ Wr2, const float* __restrict__ br2,
                            const float* __restrict__ Wr3, const float* __restrict__ br3,
                            float* __restrict__ out) {
    int b = blockIdx.x * 256 + threadIdx.x;
    float x0 = x[2 * b], x1 = x[2 * b + 1];
    float r1[8];
    #pragma unroll
    for (int j = 0; j < 8; j++)
        r1[j] = tanhf(x0 * Wr1[j] + x1 * Wr1[8 + j] + br1[j]);
    float r2[4];
    #pragma unroll
    for (int m = 0; m < 4; m++) {
        float s = br2[m];
        #pragma unroll
        for (int j = 0; j < 8; j++) s += r1[j] * Wr2[j * 4 + m];
        r2[m] = tanhf(s);
    }
    float risk = br3[0];
    #pragma unroll
    for (int m = 0; m < 4; m++) risk += r2[m] * Wr3[m];
    out[BATCH + b] = risk;
}

// ---------------------------------------------------------------------------
extern "C" void kernel_launch(void* const* d_in, const int* in_sizes, int n_in,
                              void* d_out, int out_size) {
    const float* x   = (const float*)d_in[0];
    const float* W1  = (const float*)d_in[1];
    const float* b1  = (const float*)d_in[2];
    const float* W2  = (const float*)d_in[3];
    const float* b2  = (const float*)d_in[4];
    const float* Wc  = (const float*)d_in[5];
    const float* bc  = (const float*)d_in[6];
    const float* Wr1 = (const float*)d_in[7];
    const float* br1 = (const float*)d_in[8];
    const float* Wr2 = (const float*)d_in[9];
    const float* br2 = (const float*)d_in[10];
    const float* Wr3 = (const float*)d_in[11];
    const float* br3 = (const float*)d_in[12];
    float* out = (float*)d_out;

    static bool attr_set = false;
    if (!attr_set) {
        cudaFuncSetAttribute(gemm2_mma_kernel,
                             cudaFuncAttributeMaxDynamicSharedMemorySize, GEMM_SMEM);
        attr_set = true;
    }

    init_logits_kernel<<<BATCH / 256, 256>>>(bc, out);
    w2conv_kernel<<<(HID * HID) / 1024, 256>>>(W2);
    layer1_kernel<<<BATCH / L1_ROWS, 256>>>(x, W1, b1);
    // blockIdx.x = n-tile (fastest) so the 16 CTAs sharing an A tile are adjacent
    gemm2_mma_kernel<<<dim3(HID / BN, BATCH / BM), 256, GEMM_SMEM>>>(b2, Wc, out);
    risk_kernel<<<BATCH / 256, 256>>>(x, Wr1, br1, Wr2, br2, Wr3, br3, out);
}